// round 8
// baseline (speedup 1.0000x reference)
#include <cuda_runtime.h>
#include <cuda_fp16.h>

#define NN 100000      // nodes
#define DD 64          // feature dim
#define EE 800000      // edges

#define SCAN_BLOCKS 98          // ceil(NN / 1024)
#define CHUNK 1024
#define FILL_BLOCKS 298         // blocks [0,298) do scan(+)fill in L2
#define EDGEW_BLOCKS 412        // blocks [298,710) do edge weights in L2
#define L2_GRID (FILL_BLOCKS + EDGEW_BLOCKS)

// ---------------------------------------------------------------------------
// Scratch (device globals; no allocation anywhere)
// ---------------------------------------------------------------------------
__device__ float  d_eb[3][NN * DD];      // fp32 layer-1 output per branch
__device__ __half d_Ph[NN * DD];         // e1 @ W1_top + b1  (fp16)
__device__ __half d_Qh[NN * DD];         // e1 @ W1_bot       (fp16)
__device__ __half d_gatedh[NN * DD];     // gate * e2         (fp16)
__device__ __half d_e0h[2][NN * DD];     // fp16 gather mirrors
__device__ __half d_e1h[2][NN * DD];
__device__ int    d_deg[NN];
__device__ int    d_rowptr[NN];
__device__ int    d_cursor[NN];
__device__ uint4  d_csr4[EE];            // {t, g_bits, eid, h} per CSR slot
__device__ float  d_gumcsr[EE];          // layer-1 gumbel + b2, CSR order
__device__ float  d_w[EE];               // layer-0 weights, ORIGINAL edge order
__device__ float  d_wcsr[EE];            // layer-1 weights, CSR order
__device__ int    d_agg[SCAN_BLOCKS];    // decoupled-lookback state
__device__ int    d_aggflag[SCAN_BLOCKS];
__device__ int    d_chunkdone[SCAN_BLOCKS];

__device__ __forceinline__ float fsig(float x) {
    return __fdividef(1.0f, 1.0f + __expf(-x));
}

// ---- packed f32x2 helpers --------------------------------------------------
__device__ __forceinline__ unsigned long long pack2(float x, float y) {
    unsigned long long r;
    asm("mov.b64 %0,{%1,%2};" : "=l"(r) : "f"(x), "f"(y));
    return r;
}
__device__ __forceinline__ float2 unpack2(unsigned long long v) {
    float2 r;
    asm("mov.b64 {%0,%1},%2;" : "=f"(r.x), "=f"(r.y) : "l"(v));
    return r;
}
__device__ __forceinline__ void fma2(unsigned long long& d,
                                     unsigned long long a, unsigned long long b) {
    asm("fma.rn.f32x2 %0, %1, %2, %0;" : "+l"(d) : "l"(a), "l"(b));
}

// ---- fp16 vector helpers ---------------------------------------------------
__device__ __forceinline__ void ld_h8(const __half* p, float* f) {
    uint4 r = *(const uint4*)p;
    float2 a = __half22float2(*reinterpret_cast<__half2*>(&r.x));
    float2 b = __half22float2(*reinterpret_cast<__half2*>(&r.y));
    float2 c = __half22float2(*reinterpret_cast<__half2*>(&r.z));
    float2 d = __half22float2(*reinterpret_cast<__half2*>(&r.w));
    f[0] = a.x; f[1] = a.y; f[2] = b.x; f[3] = b.y;
    f[4] = c.x; f[5] = c.y; f[6] = d.x; f[7] = d.y;
}
__device__ __forceinline__ void st_h4(__half* p, float4 v) {
    __half2 h0 = __floats2half2_rn(v.x, v.y);
    __half2 h1 = __floats2half2_rn(v.z, v.w);
    uint2 r;
    r.x = *reinterpret_cast<unsigned*>(&h0);
    r.y = *reinterpret_cast<unsigned*>(&h1);
    *(uint2*)p = r;
}
__device__ __forceinline__ void st_h8(__half* p, const float* f) {
    __half2 h0 = __floats2half2_rn(f[0], f[1]);
    __half2 h1 = __floats2half2_rn(f[2], f[3]);
    __half2 h2 = __floats2half2_rn(f[4], f[5]);
    __half2 h3 = __floats2half2_rn(f[6], f[7]);
    uint4 r;
    r.x = *reinterpret_cast<unsigned*>(&h0);
    r.y = *reinterpret_cast<unsigned*>(&h1);
    r.z = *reinterpret_cast<unsigned*>(&h2);
    r.w = *reinterpret_cast<unsigned*>(&h3);
    *(uint4*)p = r;
}
// raw uint4 (8 fp16) -> FMA into 8 fp32 accumulators, converting on the fly
__device__ __forceinline__ void fma_h8(float* acc, uint4 r, float s) {
    float2 f;
    f = __half22float2(*reinterpret_cast<__half2*>(&r.x));
    acc[0] = fmaf(s, f.x, acc[0]); acc[1] = fmaf(s, f.y, acc[1]);
    f = __half22float2(*reinterpret_cast<__half2*>(&r.y));
    acc[2] = fmaf(s, f.x, acc[2]); acc[3] = fmaf(s, f.y, acc[3]);
    f = __half22float2(*reinterpret_cast<__half2*>(&r.z));
    acc[4] = fmaf(s, f.x, acc[4]); acc[5] = fmaf(s, f.y, acc[5]);
    f = __half22float2(*reinterpret_cast<__half2*>(&r.w));
    acc[6] = fmaf(s, f.x, acc[6]); acc[7] = fmaf(s, f.y, acc[7]);
}

// ---------------------------------------------------------------------------
// L0: zero deg + lookback flags, build fp16 mirrors of emb0
// ---------------------------------------------------------------------------
__global__ void k_pre(const float4* __restrict__ emb0) {
    int i = blockIdx.x * blockDim.x + threadIdx.x;
    if (i < NN) d_deg[i] = 0;
    if (i < SCAN_BLOCKS) { d_aggflag[i] = 0; d_chunkdone[i] = 0; }
    if (i < NN * DD / 4) {
        float4 v = emb0[i];
        st_h4(&d_e0h[0][i * 4], v);
        st_h4(&d_e1h[0][i * 4], v);
    }
}

// ---------------------------------------------------------------------------
// L1 / L4: fused MLPs (+ optional degree count).
// blocks [0,296): pq      blocks [296,592): gate     blocks [592,792): count
// ---------------------------------------------------------------------------
__global__ __launch_bounds__(256) void k_mlp(
    const float* __restrict__ e1c, const float* __restrict__ e2c,
    const float* __restrict__ eW1, const float* __restrict__ eb1,  // [128,64],[64]
    const float* __restrict__ mW1, const float* __restrict__ mb1,  // [64,64],[64]
    const float* __restrict__ mW2, const float* __restrict__ mb2,  // [64,64],[64]
    const float* __restrict__ ngum,                                // [N,64]
    const int* __restrict__ h_idx)                                 // may be unused
{
    __shared__ float sW[128 * 64];   // pq: full W1. gate: [0..4095]=W1, [4096..]=W2
    __shared__ float sBa[64], sBb[64];

    int tid = threadIdx.x;
    int bid = blockIdx.x;

    if (bid >= 592) {  // count
        for (int e = (bid - 592) * 256 + tid; e < EE; e += 200 * 256)
            atomicAdd(&d_deg[h_idx[e]], 1);
        return;
    }

    int lane = tid & 31;
    int j = lane * 2;

    if (bid < 296) {
        // ---- pq: Ph = e1 @ W1_top + b1 ; Qh = e1 @ W1_bot ----
        for (int i = tid; i < 128 * 64 / 4; i += 256)
            ((float4*)sW)[i] = ((const float4*)eW1)[i];
        if (tid < 64) sBa[tid] = eb1[tid];
        __syncthreads();

        int gwarp = bid * 8 + (tid >> 5);
        int nwarps = 296 * 8;
        unsigned long long binit = *(const unsigned long long*)&sBa[j];

        for (int n0 = gwarp * 4; n0 < NN; n0 += nwarps * 4) {
            float a[4], b[4];
            unsigned long long p[4], q[4];
#pragma unroll
            for (int m = 0; m < 4; m++) {
                a[m] = e1c[(n0 + m) * 64 + lane];
                b[m] = e1c[(n0 + m) * 64 + 32 + lane];
                p[m] = binit;
                q[m] = pack2(0.0f, 0.0f);
            }
#pragma unroll
            for (int k = 0; k < 64; k++) {
                unsigned long long wt = *(const unsigned long long*)&sW[k * 64 + j];
                unsigned long long wb = *(const unsigned long long*)&sW[4096 + k * 64 + j];
#pragma unroll
                for (int m = 0; m < 4; m++) {
                    float v = __shfl_sync(0xffffffffu, (k < 32) ? a[m] : b[m], k & 31);
                    unsigned long long vv = pack2(v, v);
                    fma2(p[m], vv, wt);
                    fma2(q[m], vv, wb);
                }
            }
#pragma unroll
            for (int m = 0; m < 4; m++) {
                float2 pf = unpack2(p[m]);
                float2 qf = unpack2(q[m]);
                *(__half2*)&d_Ph[(n0 + m) * 64 + j] = __floats2half2_rn(pf.x, pf.y);
                *(__half2*)&d_Qh[(n0 + m) * 64 + j] = __floats2half2_rn(qf.x, qf.y);
            }
        }
    } else {
        // ---- gate: gatedh = sigmoid(gum + relu(e2@W1+b1)@W2 + b2) * e2 ----
        for (int i = tid; i < 64 * 64 / 4; i += 256) {
            ((float4*)sW)[i] = ((const float4*)mW1)[i];
            ((float4*)(sW + 4096))[i] = ((const float4*)mW2)[i];
        }
        if (tid < 64) { sBa[tid] = mb1[tid]; sBb[tid] = mb2[tid]; }
        __syncthreads();

        int gwarp = (bid - 296) * 8 + (tid >> 5);
        int nwarps = 296 * 8;
        unsigned long long b1init = *(const unsigned long long*)&sBa[j];
        unsigned long long b2init = *(const unsigned long long*)&sBb[j];

        for (int n0 = gwarp * 4; n0 < NN; n0 += nwarps * 4) {
            float a[4], b[4];
            unsigned long long hacc[4];
#pragma unroll
            for (int m = 0; m < 4; m++) {
                a[m] = e2c[(n0 + m) * 64 + lane];
                b[m] = e2c[(n0 + m) * 64 + 32 + lane];
                hacc[m] = b1init;
            }
#pragma unroll
            for (int k = 0; k < 64; k++) {
                unsigned long long w1 = *(const unsigned long long*)&sW[k * 64 + j];
#pragma unroll
                for (int m = 0; m < 4; m++) {
                    float v = __shfl_sync(0xffffffffu, (k < 32) ? a[m] : b[m], k & 31);
                    fma2(hacc[m], pack2(v, v), w1);
                }
            }
            float2 h[4];
            unsigned long long lg[4];
#pragma unroll
            for (int m = 0; m < 4; m++) {
                float2 hf = unpack2(hacc[m]);
                h[m] = make_float2(fmaxf(hf.x, 0.0f), fmaxf(hf.y, 0.0f));
                lg[m] = b2init;
            }
#pragma unroll
            for (int k = 0; k < 64; k++) {
                unsigned long long w2 = *(const unsigned long long*)&sW[4096 + k * 64 + j];
#pragma unroll
                for (int m = 0; m < 4; m++) {
                    float hv = __shfl_sync(0xffffffffu, (k & 1) ? h[m].y : h[m].x, k >> 1);
                    fma2(lg[m], pack2(hv, hv), w2);
                }
            }
#pragma unroll
            for (int m = 0; m < 4; m++) {
                int n = n0 + m;
                float2 lgf = unpack2(lg[m]);
                float2 gmv = *(const float2*)&ngum[n * 64 + j];
                float2 x2 = *(const float2*)&e2c[n * 64 + j];
                float gx = fsig(gmv.x + lgf.x);
                float gy = fsig(gmv.y + lgf.y);
                *(__half2*)&d_gatedh[n * 64 + j] = __floats2half2_rn(gx * x2.x, gy * x2.y);
            }
        }
    }
}

// ---------------------------------------------------------------------------
// Layer-0 edge weights, ORIGINAL edge order (overlaps CSR build in L2).
// ---------------------------------------------------------------------------
__device__ __forceinline__ void edgew_body(
    int block0, int nblocks,
    const int* __restrict__ h_idx, const int* __restrict__ t_idx,
    const float* __restrict__ gum, float b2, const float* sW2)
{
    int tid = threadIdx.x;
    int sub = tid & 7;
    int grp = tid >> 3;
    int j = sub * 8;

    for (int e = (blockIdx.x - block0) * 32 + grp; e < EE; e += nblocks * 32) {
        int h = h_idx[e];
        int t = t_idx[e];
        float p[8], q[8];
        ld_h8(&d_Ph[h * 64 + j], p);
        ld_h8(&d_Qh[t * 64 + j], q);
        float dot = 0.0f;
#pragma unroll
        for (int k = 0; k < 8; k++)
            dot = fmaf(fmaxf(p[k] + q[k], 0.0f), sW2[j + k], dot);
#pragma unroll
        for (int off = 4; off >= 1; off >>= 1)
            dot += __shfl_xor_sync(0xffffffffu, dot, off, 8);
        if (sub == 0)
            d_w[e] = fsig(gum[e] + b2 + dot);
    }
}

// ---------------------------------------------------------------------------
// L2: decoupled-lookback CSR scan + fill, overlapped with layer-0 edge weights.
// blocks [0,98): scan own 1024-node chunk, then join fill
// blocks [98,298): fill (spin on chunk-ready flags)
// blocks [298,710): edge weights (original order)
// ---------------------------------------------------------------------------
__global__ __launch_bounds__(256) void k_build_edgew(
    const int* __restrict__ h_idx, const int* __restrict__ t_idx,
    const float* __restrict__ G,
    const float* __restrict__ egum,  // [L,E] base
    const float* __restrict__ W2, const float* __restrict__ eb2)
{
    __shared__ int sScan[256];
    __shared__ int sRed[256];
    __shared__ float sW2[64];

    int tid = threadIdx.x;
    int bid = blockIdx.x;

    if (bid >= FILL_BLOCKS) {
        // ---------------- layer-0 edge weights ----------------
        if (tid < 64) sW2[tid] = W2[tid];
        __syncthreads();
        float b2 = __ldg(&eb2[0]);
        edgew_body(FILL_BLOCKS, EDGEW_BLOCKS, h_idx, t_idx, egum, b2, sW2);
        return;
    }

    if (bid < SCAN_BLOCKS) {
        // ---------------- lookback scan for chunk bid ----------------
        int nbase = bid * CHUNK + tid * 4;
        int d0 = 0, d1 = 0, d2 = 0, d3 = 0;
        if (nbase + 0 < NN) d0 = d_deg[nbase + 0];
        if (nbase + 1 < NN) d1 = d_deg[nbase + 1];
        if (nbase + 2 < NN) d2 = d_deg[nbase + 2];
        if (nbase + 3 < NN) d3 = d_deg[nbase + 3];
        int mysum = d0 + d1 + d2 + d3;
        sScan[tid] = mysum;
        __syncthreads();
        for (int off = 1; off < 256; off <<= 1) {
            int v = (tid >= off) ? sScan[tid - off] : 0;
            __syncthreads();
            sScan[tid] += v;
            __syncthreads();
        }
        int excl = sScan[tid] - mysum;
        if (tid == 255) {
            d_agg[bid] = sScan[255];
            __threadfence();
            *((volatile int*)&d_aggflag[bid]) = 1;
        }
        int pv = 0;
        if (tid < bid) {
            while (*((volatile int*)&d_aggflag[tid]) == 0) { }
            pv = d_agg[tid];
        }
        sRed[tid] = pv;
        __syncthreads();
        for (int off = 128; off >= 1; off >>= 1) {
            if (tid < off) sRed[tid] += sRed[tid + off];
            __syncthreads();
        }
        int run = sRed[0] + excl;
        if (nbase + 0 < NN) { d_rowptr[nbase + 0] = run; d_cursor[nbase + 0] = run; run += d0; }
        if (nbase + 1 < NN) { d_rowptr[nbase + 1] = run; d_cursor[nbase + 1] = run; run += d1; }
        if (nbase + 2 < NN) { d_rowptr[nbase + 2] = run; d_cursor[nbase + 2] = run; run += d2; }
        if (nbase + 3 < NN) { d_rowptr[nbase + 3] = run; d_cursor[nbase + 3] = run; run += d3; }
        __threadfence();
        __syncthreads();
        if (tid == 0) *((volatile int*)&d_chunkdone[bid]) = 1;
    }

    // ---------------- fill (all blocks [0,298), spin per chunk) ----------------
    float b2l1 = __ldg(&eb2[1]);
    for (int e = bid * 256 + tid; e < EE; e += FILL_BLOCKS * 256) {
        int h = h_idx[e];
        int c = h >> 10;
        while (*((volatile int*)&d_chunkdone[c]) == 0) { }
        int pos = atomicAdd(&d_cursor[h], 1);
        d_csr4[pos] = make_uint4((unsigned)t_idx[e], __float_as_uint(G[e]),
                                 (unsigned)e, (unsigned)h);
        d_gumcsr[pos] = egum[EE + e] + b2l1;
    }
}

// ---------------------------------------------------------------------------
// L5: layer-1 edge weights, CSR order (sequential w writes, staged gumbel)
// ---------------------------------------------------------------------------
__global__ __launch_bounds__(256) void k_edgew_csr(
    const float* __restrict__ W2)
{
    __shared__ float sW2[64];
    if (threadIdx.x < 64) sW2[threadIdx.x] = W2[threadIdx.x];
    __syncthreads();

    int tid = threadIdx.x;
    int sub = tid & 7;
    int grp = tid >> 3;
    int j = sub * 8;

    for (int pos = blockIdx.x * 32 + grp; pos < EE; pos += 1184 * 32) {
        uint4 E = d_csr4[pos];
        int t = (int)E.x;
        int h = (int)E.w;
        float p[8], q[8];
        ld_h8(&d_Ph[h * 64 + j], p);
        ld_h8(&d_Qh[t * 64 + j], q);
        float dot = 0.0f;
#pragma unroll
        for (int k = 0; k < 8; k++)
            dot = fmaf(fmaxf(p[k] + q[k], 0.0f), sW2[j + k], dot);
#pragma unroll
        for (int off = 4; off >= 1; off >>= 1)
            dot += __shfl_xor_sync(0xffffffffu, dot, off, 8);
        if (sub == 0)
            d_wcsr[pos] = fsig(d_gumcsr[pos] + dot);
    }
}

// ---------------------------------------------------------------------------
// L3/L6: per-node 3-branch SpMM + row norm + residual.  8 threads/node.
// 2-edge software pipeline; features staged raw (uint4) and converted at FMA.
// wmode=0: w = warr[E.z] (original order).  wmode=1: w = warr[pos] (CSR order).
// last=0: write fp32 state + fp16 mirrors.   last=1: out = emb0 + c + o.
// ---------------------------------------------------------------------------
__global__ __launch_bounds__(256) void k_gather(
    const float* __restrict__ e0c, const float* __restrict__ e1c,
    const float* __restrict__ e2c,
    const __half* __restrict__ e0h, const __half* __restrict__ e1h,
    float* __restrict__ e0n, float* __restrict__ e1n, float* __restrict__ e2n,
    __half* __restrict__ e0nh, __half* __restrict__ e1nh,
    const float* __restrict__ emb0, float* __restrict__ out,
    const float* __restrict__ warr, int wmode, int last)
{
    int node = blockIdx.x * 32 + (threadIdx.x >> 3);  // 3125 * 32 = 100000
    int sub = threadIdx.x & 7;
    int j = sub * 8;

    int p = d_rowptr[node];
    int rem = d_deg[node];

    float rowsum = 0.0f;
    float a0[8], a1[8], a2[8];
#pragma unroll
    for (int k = 0; k < 8; k++) { a0[k] = 0.f; a1[k] = 0.f; a2[k] = 0.f; }

    // odd leading edge
    if (rem & 1) {
        uint4 E = d_csr4[p];
        float w = wmode ? warr[p] : warr[E.z];
        float g = __uint_as_float(E.y);
        int t = (int)E.x;
        uint4 r0 = *(const uint4*)&e0h[t * 64 + j];
        uint4 r1 = *(const uint4*)&e1h[t * 64 + j];
        uint4 r2 = *(const uint4*)&d_gatedh[t * 64 + j];
        rowsum += w;
        fma_h8(a0, r0, g);
        fma_h8(a1, r1, w);
        fma_h8(a2, r2, g);
        p++; rem--;
    }

    if (rem > 0) {
        // preload first pair
        uint4 Ea = d_csr4[p];
        uint4 Eb = d_csr4[p + 1];
        float wa = wmode ? warr[p] : warr[Ea.z];
        float wb = wmode ? warr[p + 1] : warr[Eb.z];

        for (int it = 0; it < rem; it += 2) {
            uint4 Ca = Ea, Cb = Eb;
            float cwa = wa, cwb = wb;
            if (it + 3 < rem) {
                int np = p + it + 2;
                Ea = d_csr4[np];
                Eb = d_csr4[np + 1];
                wa = wmode ? warr[np] : warr[Ea.z];
                wb = wmode ? warr[np + 1] : warr[Eb.z];
            }
            int ta = (int)Ca.x, tb = (int)Cb.x;
            float ga = __uint_as_float(Ca.y), gb = __uint_as_float(Cb.y);
            // issue all six independent 16B feature loads
            uint4 r0a = *(const uint4*)&e0h[ta * 64 + j];
            uint4 r1a = *(const uint4*)&e1h[ta * 64 + j];
            uint4 r2a = *(const uint4*)&d_gatedh[ta * 64 + j];
            uint4 r0b = *(const uint4*)&e0h[tb * 64 + j];
            uint4 r1b = *(const uint4*)&e1h[tb * 64 + j];
            uint4 r2b = *(const uint4*)&d_gatedh[tb * 64 + j];
            rowsum += cwa + cwb;
            fma_h8(a0, r0a, ga);
            fma_h8(a1, r1a, cwa);
            fma_h8(a2, r2a, ga);
            fma_h8(a0, r0b, gb);
            fma_h8(a1, r1b, cwb);
            fma_h8(a2, r2b, gb);
        }
    }

    float dinv = (rowsum > 0.0f) ? (1.0f / rowsum) : 0.0f;

    float c0[8], c1[8], c2[8], o0[8], o1[8], o2[8];
    *(float4*)&c0[0] = *(const float4*)&e0c[node * 64 + j];
    *(float4*)&c0[4] = *(const float4*)&e0c[node * 64 + j + 4];
    *(float4*)&c1[0] = *(const float4*)&e1c[node * 64 + j];
    *(float4*)&c1[4] = *(const float4*)&e1c[node * 64 + j + 4];
    *(float4*)&c2[0] = *(const float4*)&e2c[node * 64 + j];
    *(float4*)&c2[4] = *(const float4*)&e2c[node * 64 + j + 4];
#pragma unroll
    for (int k = 0; k < 8; k++) {
        o0[k] = c0[k] + a0[k];
        o1[k] = fmaf(dinv, a1[k], c1[k]);
        o2[k] = c2[k] + a2[k];
    }

    if (!last) {
        *(float4*)&e0n[node * 64 + j]     = *(float4*)&o0[0];
        *(float4*)&e0n[node * 64 + j + 4] = *(float4*)&o0[4];
        *(float4*)&e1n[node * 64 + j]     = *(float4*)&o1[0];
        *(float4*)&e1n[node * 64 + j + 4] = *(float4*)&o1[4];
        *(float4*)&e2n[node * 64 + j]     = *(float4*)&o2[0];
        *(float4*)&e2n[node * 64 + j + 4] = *(float4*)&o2[4];
        st_h8(&e0nh[node * 64 + j], o0);
        st_h8(&e1nh[node * 64 + j], o1);
    } else {
        float z[8];
        *(float4*)&z[0] = *(const float4*)&emb0[node * 64 + j];
        *(float4*)&z[4] = *(const float4*)&emb0[node * 64 + j + 4];
        const int per = NN * DD;
        float r[8];
#pragma unroll
        for (int k = 0; k < 8; k++) r[k] = z[k] + c0[k] + o0[k];
        *(float4*)&out[0 * per + node * 64 + j]     = *(float4*)&r[0];
        *(float4*)&out[0 * per + node * 64 + j + 4] = *(float4*)&r[4];
#pragma unroll
        for (int k = 0; k < 8; k++) r[k] = z[k] + c1[k] + o1[k];
        *(float4*)&out[1 * per + node * 64 + j]     = *(float4*)&r[0];
        *(float4*)&out[1 * per + node * 64 + j + 4] = *(float4*)&r[4];
#pragma unroll
        for (int k = 0; k < 8; k++) r[k] = z[k] + c2[k] + o2[k];
        *(float4*)&out[2 * per + node * 64 + j]     = *(float4*)&r[0];
        *(float4*)&out[2 * per + node * 64 + j + 4] = *(float4*)&r[4];
    }
}

// ---------------------------------------------------------------------------
// Host launcher (graph-capturable: launches only)
// ---------------------------------------------------------------------------
extern "C" void kernel_launch(void* const* d_in, const int* in_sizes, int n_in,
                              void* d_out, int out_size) {
    const float* emb0 = (const float*)d_in[0];
    const int*   hI   = (const int*)  d_in[1];
    const int*   tI   = (const int*)  d_in[2];
    const float* G    = (const float*)d_in[3];
    const float* egum = (const float*)d_in[4];   // [L,E]
    const float* ngum = (const float*)d_in[5];   // [L,N,D]
    const float* eW1  = (const float*)d_in[6];   // [L,128,64]
    const float* eb1  = (const float*)d_in[7];   // [L,64]
    const float* eW2  = (const float*)d_in[8];   // [L,64,1]
    const float* eb2  = (const float*)d_in[9];   // [L,1]
    const float* mW1  = (const float*)d_in[10];  // [L,64,64]
    const float* mb1  = (const float*)d_in[11];  // [L,64]
    const float* mW2  = (const float*)d_in[12];  // [L,64,64]
    const float* mb2  = (const float*)d_in[13];  // [L,64]
    float* out = (float*)d_out;

    float* base;
    cudaGetSymbolAddress((void**)&base, d_eb);
    __half* h0base;
    cudaGetSymbolAddress((void**)&h0base, d_e0h);
    __half* h1base;
    cudaGetSymbolAddress((void**)&h1base, d_e1h);
    float* wbase;
    cudaGetSymbolAddress((void**)&wbase, d_w);
    float* wcsrbase;
    cudaGetSymbolAddress((void**)&wcsrbase, d_wcsr);

    float* ebuf[3];
    for (int b = 0; b < 3; b++)
        ebuf[b] = base + (size_t)b * NN * DD;
    __half* e0hbuf[2] = { h0base, h0base + (size_t)NN * DD };
    __half* e1hbuf[2] = { h1base, h1base + (size_t)NN * DD };

    // L0: zero + mirrors + flags
    k_pre<<<(NN * DD / 4 + 255) / 256, 256>>>((const float4*)emb0);

    // L1: layer-0 MLPs + degree count
    k_mlp<<<792, 256>>>(emb0, emb0, eW1, eb1, mW1, mb1, mW2, mb2, ngum, hI);

    // L2: CSR scan+fill overlapped with layer-0 edge weights
    k_build_edgew<<<L2_GRID, 256>>>(hI, tI, G, egum, eW2, eb2);

    // L3: layer-0 gather  <-- profiled launch (index 3)
    k_gather<<<3125, 256>>>(emb0, emb0, emb0, e0hbuf[0], e1hbuf[0],
                            ebuf[0], ebuf[1], ebuf[2],
                            e0hbuf[1], e1hbuf[1],
                            emb0, out, wbase, 0, 0);

    // L4: layer-1 MLPs
    k_mlp<<<592, 256>>>(ebuf[1], ebuf[2],
                        eW1 + 128 * 64, eb1 + 64,
                        mW1 + 64 * 64, mb1 + 64, mW2 + 64 * 64, mb2 + 64,
                        ngum + (size_t)NN * 64, hI);

    // L5: layer-1 edge weights (CSR order)
    k_edgew_csr<<<1184, 256>>>(eW2 + 64);

    // L6: layer-1 gather + final output
    k_gather<<<3125, 256>>>(ebuf[0], ebuf[1], ebuf[2], e0hbuf[1], e1hbuf[1],
                            ebuf[0], ebuf[1], ebuf[2],
                            e0hbuf[0], e1hbuf[0],
                            emb0, out, wcsrbase, 1, 1);
}

// round 9
// speedup vs baseline: 1.0074x; 1.0074x over previous
#include <cuda_runtime.h>
#include <cuda_fp16.h>

#define NN 100000      // nodes
#define DD 64          // feature dim
#define EE 800000      // edges

#define SCAN_BLOCKS 98          // ceil(NN / 1024)
#define CHUNK 1024
#define FILL_BLOCKS 298         // blocks [0,298) do scan(+)fill in L2
#define EDGEW_BLOCKS 412        // blocks [298,710) do edge weights in L2
#define L2_GRID (FILL_BLOCKS + EDGEW_BLOCKS)

// ---------------------------------------------------------------------------
// Scratch (device globals; no allocation anywhere)
// ---------------------------------------------------------------------------
__device__ float  d_eb[3][NN * DD];      // fp32 layer-1 output per branch
__device__ __half d_Ph[NN * DD];         // e1 @ W1_top + b1  (fp16)
__device__ __half d_Qh[NN * DD];         // e1 @ W1_bot       (fp16)
__device__ __half d_gatedh[NN * DD];     // gate * e2         (fp16)
__device__ __half d_e0h[2][NN * DD];     // fp16 gather mirrors
__device__ __half d_e1h[2][NN * DD];
__device__ int    d_deg[NN];
__device__ int    d_rowptr[NN];
__device__ int    d_cursor[NN];
__device__ uint4  d_csr4[EE];            // {t, g_bits, eid, h} per CSR slot
__device__ float  d_gumcsr[EE];          // layer-1 gumbel + b2, CSR order
__device__ float  d_w[EE];               // layer-0 weights, ORIGINAL edge order
__device__ float  d_wcsr[EE];            // layer-1 weights, CSR order
__device__ int    d_agg[SCAN_BLOCKS];    // decoupled-lookback state
__device__ int    d_aggflag[SCAN_BLOCKS];
__device__ int    d_chunkdone[SCAN_BLOCKS];

__device__ __forceinline__ float fsig(float x) {
    return __fdividef(1.0f, 1.0f + __expf(-x));
}

// ---- packed f32x2 helpers --------------------------------------------------
__device__ __forceinline__ unsigned long long pack2(float x, float y) {
    unsigned long long r;
    asm("mov.b64 %0,{%1,%2};" : "=l"(r) : "f"(x), "f"(y));
    return r;
}
__device__ __forceinline__ float2 unpack2(unsigned long long v) {
    float2 r;
    asm("mov.b64 {%0,%1},%2;" : "=f"(r.x), "=f"(r.y) : "l"(v));
    return r;
}
__device__ __forceinline__ void fma2(unsigned long long& d,
                                     unsigned long long a, unsigned long long b) {
    asm("fma.rn.f32x2 %0, %1, %2, %0;" : "+l"(d) : "l"(a), "l"(b));
}

// ---- fp16 vector helpers ---------------------------------------------------
__device__ __forceinline__ void ld_h8(const __half* p, float* f) {
    uint4 r = *(const uint4*)p;
    float2 a = __half22float2(*reinterpret_cast<__half2*>(&r.x));
    float2 b = __half22float2(*reinterpret_cast<__half2*>(&r.y));
    float2 c = __half22float2(*reinterpret_cast<__half2*>(&r.z));
    float2 d = __half22float2(*reinterpret_cast<__half2*>(&r.w));
    f[0] = a.x; f[1] = a.y; f[2] = b.x; f[3] = b.y;
    f[4] = c.x; f[5] = c.y; f[6] = d.x; f[7] = d.y;
}
__device__ __forceinline__ void st_h4(__half* p, float4 v) {
    __half2 h0 = __floats2half2_rn(v.x, v.y);
    __half2 h1 = __floats2half2_rn(v.z, v.w);
    uint2 r;
    r.x = *reinterpret_cast<unsigned*>(&h0);
    r.y = *reinterpret_cast<unsigned*>(&h1);
    *(uint2*)p = r;
}
__device__ __forceinline__ void st_h8(__half* p, const float* f) {
    __half2 h0 = __floats2half2_rn(f[0], f[1]);
    __half2 h1 = __floats2half2_rn(f[2], f[3]);
    __half2 h2 = __floats2half2_rn(f[4], f[5]);
    __half2 h3 = __floats2half2_rn(f[6], f[7]);
    uint4 r;
    r.x = *reinterpret_cast<unsigned*>(&h0);
    r.y = *reinterpret_cast<unsigned*>(&h1);
    r.z = *reinterpret_cast<unsigned*>(&h2);
    r.w = *reinterpret_cast<unsigned*>(&h3);
    *(uint4*)p = r;
}
// raw uint4 (8 fp16) -> FMA into 8 fp32 accumulators, converting on the fly
__device__ __forceinline__ void fma_h8(float* acc, uint4 r, float s) {
    float2 f;
    f = __half22float2(*reinterpret_cast<__half2*>(&r.x));
    acc[0] = fmaf(s, f.x, acc[0]); acc[1] = fmaf(s, f.y, acc[1]);
    f = __half22float2(*reinterpret_cast<__half2*>(&r.y));
    acc[2] = fmaf(s, f.x, acc[2]); acc[3] = fmaf(s, f.y, acc[3]);
    f = __half22float2(*reinterpret_cast<__half2*>(&r.z));
    acc[4] = fmaf(s, f.x, acc[4]); acc[5] = fmaf(s, f.y, acc[5]);
    f = __half22float2(*reinterpret_cast<__half2*>(&r.w));
    acc[6] = fmaf(s, f.x, acc[6]); acc[7] = fmaf(s, f.y, acc[7]);
}

// ---------------------------------------------------------------------------
// L0: zero deg + lookback flags, build fp16 mirrors of emb0
// ---------------------------------------------------------------------------
__global__ void k_pre(const float4* __restrict__ emb0) {
    int i = blockIdx.x * blockDim.x + threadIdx.x;
    if (i < NN) d_deg[i] = 0;
    if (i < SCAN_BLOCKS) { d_aggflag[i] = 0; d_chunkdone[i] = 0; }
    if (i < NN * DD / 4) {
        float4 v = emb0[i];
        st_h4(&d_e0h[0][i * 4], v);
        st_h4(&d_e1h[0][i * 4], v);
    }
}

// ---------------------------------------------------------------------------
// L1 / L4: fused MLPs (+ optional degree count).
// blocks [0,296): pq      blocks [296,592): gate     blocks [592,792): count
// ---------------------------------------------------------------------------
__global__ __launch_bounds__(256) void k_mlp(
    const float* __restrict__ e1c, const float* __restrict__ e2c,
    const float* __restrict__ eW1, const float* __restrict__ eb1,  // [128,64],[64]
    const float* __restrict__ mW1, const float* __restrict__ mb1,  // [64,64],[64]
    const float* __restrict__ mW2, const float* __restrict__ mb2,  // [64,64],[64]
    const float* __restrict__ ngum,                                // [N,64]
    const int* __restrict__ h_idx)                                 // may be unused
{
    __shared__ float sW[128 * 64];   // pq: full W1. gate: [0..4095]=W1, [4096..]=W2
    __shared__ float sBa[64], sBb[64];

    int tid = threadIdx.x;
    int bid = blockIdx.x;

    if (bid >= 592) {  // count
        for (int e = (bid - 592) * 256 + tid; e < EE; e += 200 * 256)
            atomicAdd(&d_deg[h_idx[e]], 1);
        return;
    }

    int lane = tid & 31;
    int j = lane * 2;

    if (bid < 296) {
        // ---- pq: Ph = e1 @ W1_top + b1 ; Qh = e1 @ W1_bot ----
        for (int i = tid; i < 128 * 64 / 4; i += 256)
            ((float4*)sW)[i] = ((const float4*)eW1)[i];
        if (tid < 64) sBa[tid] = eb1[tid];
        __syncthreads();

        int gwarp = bid * 8 + (tid >> 5);
        int nwarps = 296 * 8;
        unsigned long long binit = *(const unsigned long long*)&sBa[j];

        for (int n0 = gwarp * 4; n0 < NN; n0 += nwarps * 4) {
            float a[4], b[4];
            unsigned long long p[4], q[4];
#pragma unroll
            for (int m = 0; m < 4; m++) {
                a[m] = e1c[(n0 + m) * 64 + lane];
                b[m] = e1c[(n0 + m) * 64 + 32 + lane];
                p[m] = binit;
                q[m] = pack2(0.0f, 0.0f);
            }
#pragma unroll
            for (int k = 0; k < 64; k++) {
                unsigned long long wt = *(const unsigned long long*)&sW[k * 64 + j];
                unsigned long long wb = *(const unsigned long long*)&sW[4096 + k * 64 + j];
#pragma unroll
                for (int m = 0; m < 4; m++) {
                    float v = __shfl_sync(0xffffffffu, (k < 32) ? a[m] : b[m], k & 31);
                    unsigned long long vv = pack2(v, v);
                    fma2(p[m], vv, wt);
                    fma2(q[m], vv, wb);
                }
            }
#pragma unroll
            for (int m = 0; m < 4; m++) {
                float2 pf = unpack2(p[m]);
                float2 qf = unpack2(q[m]);
                *(__half2*)&d_Ph[(n0 + m) * 64 + j] = __floats2half2_rn(pf.x, pf.y);
                *(__half2*)&d_Qh[(n0 + m) * 64 + j] = __floats2half2_rn(qf.x, qf.y);
            }
        }
    } else {
        // ---- gate: gatedh = sigmoid(gum + relu(e2@W1+b1)@W2 + b2) * e2 ----
        for (int i = tid; i < 64 * 64 / 4; i += 256) {
            ((float4*)sW)[i] = ((const float4*)mW1)[i];
            ((float4*)(sW + 4096))[i] = ((const float4*)mW2)[i];
        }
        if (tid < 64) { sBa[tid] = mb1[tid]; sBb[tid] = mb2[tid]; }
        __syncthreads();

        int gwarp = (bid - 296) * 8 + (tid >> 5);
        int nwarps = 296 * 8;
        unsigned long long b1init = *(const unsigned long long*)&sBa[j];
        unsigned long long b2init = *(const unsigned long long*)&sBb[j];

        for (int n0 = gwarp * 4; n0 < NN; n0 += nwarps * 4) {
            float a[4], b[4];
            unsigned long long hacc[4];
#pragma unroll
            for (int m = 0; m < 4; m++) {
                a[m] = e2c[(n0 + m) * 64 + lane];
                b[m] = e2c[(n0 + m) * 64 + 32 + lane];
                hacc[m] = b1init;
            }
#pragma unroll
            for (int k = 0; k < 64; k++) {
                unsigned long long w1 = *(const unsigned long long*)&sW[k * 64 + j];
#pragma unroll
                for (int m = 0; m < 4; m++) {
                    float v = __shfl_sync(0xffffffffu, (k < 32) ? a[m] : b[m], k & 31);
                    fma2(hacc[m], pack2(v, v), w1);
                }
            }
            float2 h[4];
            unsigned long long lg[4];
#pragma unroll
            for (int m = 0; m < 4; m++) {
                float2 hf = unpack2(hacc[m]);
                h[m] = make_float2(fmaxf(hf.x, 0.0f), fmaxf(hf.y, 0.0f));
                lg[m] = b2init;
            }
#pragma unroll
            for (int k = 0; k < 64; k++) {
                unsigned long long w2 = *(const unsigned long long*)&sW[4096 + k * 64 + j];
#pragma unroll
                for (int m = 0; m < 4; m++) {
                    float hv = __shfl_sync(0xffffffffu, (k & 1) ? h[m].y : h[m].x, k >> 1);
                    fma2(lg[m], pack2(hv, hv), w2);
                }
            }
#pragma unroll
            for (int m = 0; m < 4; m++) {
                int n = n0 + m;
                float2 lgf = unpack2(lg[m]);
                float2 gmv = *(const float2*)&ngum[n * 64 + j];
                float2 x2 = *(const float2*)&e2c[n * 64 + j];
                float gx = fsig(gmv.x + lgf.x);
                float gy = fsig(gmv.y + lgf.y);
                *(__half2*)&d_gatedh[n * 64 + j] = __floats2half2_rn(gx * x2.x, gy * x2.y);
            }
        }
    }
}

// ---------------------------------------------------------------------------
// Layer-0 edge weights, ORIGINAL edge order (overlaps CSR build in L2).
// ---------------------------------------------------------------------------
__device__ __forceinline__ void edgew_body(
    int block0, int nblocks,
    const int* __restrict__ h_idx, const int* __restrict__ t_idx,
    const float* __restrict__ gum, float b2, const float* sW2)
{
    int tid = threadIdx.x;
    int sub = tid & 7;
    int grp = tid >> 3;
    int j = sub * 8;

    for (int e = (blockIdx.x - block0) * 32 + grp; e < EE; e += nblocks * 32) {
        int h = h_idx[e];
        int t = t_idx[e];
        float p[8], q[8];
        ld_h8(&d_Ph[h * 64 + j], p);
        ld_h8(&d_Qh[t * 64 + j], q);
        float dot = 0.0f;
#pragma unroll
        for (int k = 0; k < 8; k++)
            dot = fmaf(fmaxf(p[k] + q[k], 0.0f), sW2[j + k], dot);
#pragma unroll
        for (int off = 4; off >= 1; off >>= 1)
            dot += __shfl_xor_sync(0xffffffffu, dot, off, 8);
        if (sub == 0)
            d_w[e] = fsig(gum[e] + b2 + dot);
    }
}

// ---------------------------------------------------------------------------
// L2: decoupled-lookback CSR scan + fill, overlapped with layer-0 edge weights.
// blocks [0,98): scan own 1024-node chunk, then join fill
// blocks [98,298): fill (spin on chunk-ready flags)
// blocks [298,710): edge weights (original order)
// ---------------------------------------------------------------------------
__global__ __launch_bounds__(256) void k_build_edgew(
    const int* __restrict__ h_idx, const int* __restrict__ t_idx,
    const float* __restrict__ G,
    const float* __restrict__ egum,  // [L,E] base
    const float* __restrict__ W2, const float* __restrict__ eb2)
{
    __shared__ int sScan[256];
    __shared__ int sRed[256];
    __shared__ float sW2[64];

    int tid = threadIdx.x;
    int bid = blockIdx.x;

    if (bid >= FILL_BLOCKS) {
        // ---------------- layer-0 edge weights ----------------
        if (tid < 64) sW2[tid] = W2[tid];
        __syncthreads();
        float b2 = __ldg(&eb2[0]);
        edgew_body(FILL_BLOCKS, EDGEW_BLOCKS, h_idx, t_idx, egum, b2, sW2);
        return;
    }

    if (bid < SCAN_BLOCKS) {
        // ---------------- lookback scan for chunk bid ----------------
        int nbase = bid * CHUNK + tid * 4;
        int d0 = 0, d1 = 0, d2 = 0, d3 = 0;
        if (nbase + 0 < NN) d0 = d_deg[nbase + 0];
        if (nbase + 1 < NN) d1 = d_deg[nbase + 1];
        if (nbase + 2 < NN) d2 = d_deg[nbase + 2];
        if (nbase + 3 < NN) d3 = d_deg[nbase + 3];
        int mysum = d0 + d1 + d2 + d3;
        sScan[tid] = mysum;
        __syncthreads();
        for (int off = 1; off < 256; off <<= 1) {
            int v = (tid >= off) ? sScan[tid - off] : 0;
            __syncthreads();
            sScan[tid] += v;
            __syncthreads();
        }
        int excl = sScan[tid] - mysum;
        if (tid == 255) {
            d_agg[bid] = sScan[255];
            __threadfence();
            *((volatile int*)&d_aggflag[bid]) = 1;
        }
        int pv = 0;
        if (tid < bid) {
            while (*((volatile int*)&d_aggflag[tid]) == 0) { }
            pv = d_agg[tid];
        }
        sRed[tid] = pv;
        __syncthreads();
        for (int off = 128; off >= 1; off >>= 1) {
            if (tid < off) sRed[tid] += sRed[tid + off];
            __syncthreads();
        }
        int run = sRed[0] + excl;
        if (nbase + 0 < NN) { d_rowptr[nbase + 0] = run; d_cursor[nbase + 0] = run; run += d0; }
        if (nbase + 1 < NN) { d_rowptr[nbase + 1] = run; d_cursor[nbase + 1] = run; run += d1; }
        if (nbase + 2 < NN) { d_rowptr[nbase + 2] = run; d_cursor[nbase + 2] = run; run += d2; }
        if (nbase + 3 < NN) { d_rowptr[nbase + 3] = run; d_cursor[nbase + 3] = run; run += d3; }
        __threadfence();
        __syncthreads();
        if (tid == 0) *((volatile int*)&d_chunkdone[bid]) = 1;
    }

    // ---------------- fill (all blocks [0,298), spin per chunk) ----------------
    float b2l1 = __ldg(&eb2[1]);
    for (int e = bid * 256 + tid; e < EE; e += FILL_BLOCKS * 256) {
        int h = h_idx[e];
        int c = h >> 10;
        while (*((volatile int*)&d_chunkdone[c]) == 0) { }
        int pos = atomicAdd(&d_cursor[h], 1);
        d_csr4[pos] = make_uint4((unsigned)t_idx[e], __float_as_uint(G[e]),
                                 (unsigned)e, (unsigned)h);
        d_gumcsr[pos] = egum[EE + e] + b2l1;
    }
}

// ---------------------------------------------------------------------------
// L5: layer-1 edge weights, CSR order (sequential w writes, staged gumbel)
// ---------------------------------------------------------------------------
__global__ __launch_bounds__(256) void k_edgew_csr(
    const float* __restrict__ W2)
{
    __shared__ float sW2[64];
    if (threadIdx.x < 64) sW2[threadIdx.x] = W2[threadIdx.x];
    __syncthreads();

    int tid = threadIdx.x;
    int sub = tid & 7;
    int grp = tid >> 3;
    int j = sub * 8;

    for (int pos = blockIdx.x * 32 + grp; pos < EE; pos += 1184 * 32) {
        uint4 E = d_csr4[pos];
        int t = (int)E.x;
        int h = (int)E.w;
        float p[8], q[8];
        ld_h8(&d_Ph[h * 64 + j], p);
        ld_h8(&d_Qh[t * 64 + j], q);
        float dot = 0.0f;
#pragma unroll
        for (int k = 0; k < 8; k++)
            dot = fmaf(fmaxf(p[k] + q[k], 0.0f), sW2[j + k], dot);
#pragma unroll
        for (int off = 4; off >= 1; off >>= 1)
            dot += __shfl_xor_sync(0xffffffffu, dot, off, 8);
        if (sub == 0)
            d_wcsr[pos] = fsig(d_gumcsr[pos] + dot);
    }
}

// ---------------------------------------------------------------------------
// L3/L6: per-node 3-branch SpMM + row norm + residual.  8 threads/node.
// 2-edge software pipeline; features staged raw (uint4) and converted at FMA.
// wmode=0: w = warr[E.z] (original order).  wmode=1: w = warr[pos] (CSR order).
// last=0: write fp32 state + fp16 mirrors.   last=1: out = emb0 + c + o.
// ---------------------------------------------------------------------------
__global__ __launch_bounds__(256) void k_gather(
    const float* __restrict__ e0c, const float* __restrict__ e1c,
    const float* __restrict__ e2c,
    const __half* __restrict__ e0h, const __half* __restrict__ e1h,
    float* __restrict__ e0n, float* __restrict__ e1n, float* __restrict__ e2n,
    __half* __restrict__ e0nh, __half* __restrict__ e1nh,
    const float* __restrict__ emb0, float* __restrict__ out,
    const float* __restrict__ warr, int wmode, int last)
{
    int node = blockIdx.x * 32 + (threadIdx.x >> 3);  // 3125 * 32 = 100000
    int sub = threadIdx.x & 7;
    int j = sub * 8;

    int p = d_rowptr[node];
    int rem = d_deg[node];

    float rowsum = 0.0f;
    float a0[8], a1[8], a2[8];
#pragma unroll
    for (int k = 0; k < 8; k++) { a0[k] = 0.f; a1[k] = 0.f; a2[k] = 0.f; }

    // odd leading edge
    if (rem & 1) {
        uint4 E = d_csr4[p];
        float w = wmode ? warr[p] : warr[E.z];
        float g = __uint_as_float(E.y);
        int t = (int)E.x;
        uint4 r0 = *(const uint4*)&e0h[t * 64 + j];
        uint4 r1 = *(const uint4*)&e1h[t * 64 + j];
        uint4 r2 = *(const uint4*)&d_gatedh[t * 64 + j];
        rowsum += w;
        fma_h8(a0, r0, g);
        fma_h8(a1, r1, w);
        fma_h8(a2, r2, g);
        p++; rem--;
    }

    if (rem > 0) {
        // preload first pair
        uint4 Ea = d_csr4[p];
        uint4 Eb = d_csr4[p + 1];
        float wa = wmode ? warr[p] : warr[Ea.z];
        float wb = wmode ? warr[p + 1] : warr[Eb.z];

        for (int it = 0; it < rem; it += 2) {
            uint4 Ca = Ea, Cb = Eb;
            float cwa = wa, cwb = wb;
            if (it + 3 < rem) {
                int np = p + it + 2;
                Ea = d_csr4[np];
                Eb = d_csr4[np + 1];
                wa = wmode ? warr[np] : warr[Ea.z];
                wb = wmode ? warr[np + 1] : warr[Eb.z];
            }
            int ta = (int)Ca.x, tb = (int)Cb.x;
            float ga = __uint_as_float(Ca.y), gb = __uint_as_float(Cb.y);
            // issue all six independent 16B feature loads
            uint4 r0a = *(const uint4*)&e0h[ta * 64 + j];
            uint4 r1a = *(const uint4*)&e1h[ta * 64 + j];
            uint4 r2a = *(const uint4*)&d_gatedh[ta * 64 + j];
            uint4 r0b = *(const uint4*)&e0h[tb * 64 + j];
            uint4 r1b = *(const uint4*)&e1h[tb * 64 + j];
            uint4 r2b = *(const uint4*)&d_gatedh[tb * 64 + j];
            rowsum += cwa + cwb;
            fma_h8(a0, r0a, ga);
            fma_h8(a1, r1a, cwa);
            fma_h8(a2, r2a, ga);
            fma_h8(a0, r0b, gb);
            fma_h8(a1, r1b, cwb);
            fma_h8(a2, r2b, gb);
        }
    }

    float dinv = (rowsum > 0.0f) ? (1.0f / rowsum) : 0.0f;

    float c0[8], c1[8], c2[8], o0[8], o1[8], o2[8];
    *(float4*)&c0[0] = *(const float4*)&e0c[node * 64 + j];
    *(float4*)&c0[4] = *(const float4*)&e0c[node * 64 + j + 4];
    *(float4*)&c1[0] = *(const float4*)&e1c[node * 64 + j];
    *(float4*)&c1[4] = *(const float4*)&e1c[node * 64 + j + 4];
    *(float4*)&c2[0] = *(const float4*)&e2c[node * 64 + j];
    *(float4*)&c2[4] = *(const float4*)&e2c[node * 64 + j + 4];
#pragma unroll
    for (int k = 0; k < 8; k++) {
        o0[k] = c0[k] + a0[k];
        o1[k] = fmaf(dinv, a1[k], c1[k]);
        o2[k] = c2[k] + a2[k];
    }

    if (!last) {
        *(float4*)&e0n[node * 64 + j]     = *(float4*)&o0[0];
        *(float4*)&e0n[node * 64 + j + 4] = *(float4*)&o0[4];
        *(float4*)&e1n[node * 64 + j]     = *(float4*)&o1[0];
        *(float4*)&e1n[node * 64 + j + 4] = *(float4*)&o1[4];
        *(float4*)&e2n[node * 64 + j]     = *(float4*)&o2[0];
        *(float4*)&e2n[node * 64 + j + 4] = *(float4*)&o2[4];
        st_h8(&e0nh[node * 64 + j], o0);
        st_h8(&e1nh[node * 64 + j], o1);
    } else {
        float z[8];
        *(float4*)&z[0] = *(const float4*)&emb0[node * 64 + j];
        *(float4*)&z[4] = *(const float4*)&emb0[node * 64 + j + 4];
        const int per = NN * DD;
        float r[8];
#pragma unroll
        for (int k = 0; k < 8; k++) r[k] = z[k] + c0[k] + o0[k];
        *(float4*)&out[0 * per + node * 64 + j]     = *(float4*)&r[0];
        *(float4*)&out[0 * per + node * 64 + j + 4] = *(float4*)&r[4];
#pragma unroll
        for (int k = 0; k < 8; k++) r[k] = z[k] + c1[k] + o1[k];
        *(float4*)&out[1 * per + node * 64 + j]     = *(float4*)&r[0];
        *(float4*)&out[1 * per + node * 64 + j + 4] = *(float4*)&r[4];
#pragma unroll
        for (int k = 0; k < 8; k++) r[k] = z[k] + c2[k] + o2[k];
        *(float4*)&out[2 * per + node * 64 + j]     = *(float4*)&r[0];
        *(float4*)&out[2 * per + node * 64 + j + 4] = *(float4*)&r[4];
    }
}

// ---------------------------------------------------------------------------
// Host launcher (graph-capturable: launches only)
// ---------------------------------------------------------------------------
extern "C" void kernel_launch(void* const* d_in, const int* in_sizes, int n_in,
                              void* d_out, int out_size) {
    const float* emb0 = (const float*)d_in[0];
    const int*   hI   = (const int*)  d_in[1];
    const int*   tI   = (const int*)  d_in[2];
    const float* G    = (const float*)d_in[3];
    const float* egum = (const float*)d_in[4];   // [L,E]
    const float* ngum = (const float*)d_in[5];   // [L,N,D]
    const float* eW1  = (const float*)d_in[6];   // [L,128,64]
    const float* eb1  = (const float*)d_in[7];   // [L,64]
    const float* eW2  = (const float*)d_in[8];   // [L,64,1]
    const float* eb2  = (const float*)d_in[9];   // [L,1]
    const float* mW1  = (const float*)d_in[10];  // [L,64,64]
    const float* mb1  = (const float*)d_in[11];  // [L,64]
    const float* mW2  = (const float*)d_in[12];  // [L,64,64]
    const float* mb2  = (const float*)d_in[13];  // [L,64]
    float* out = (float*)d_out;

    float* base;
    cudaGetSymbolAddress((void**)&base, d_eb);
    __half* h0base;
    cudaGetSymbolAddress((void**)&h0base, d_e0h);
    __half* h1base;
    cudaGetSymbolAddress((void**)&h1base, d_e1h);
    float* wbase;
    cudaGetSymbolAddress((void**)&wbase, d_w);
    float* wcsrbase;
    cudaGetSymbolAddress((void**)&wcsrbase, d_wcsr);

    float* ebuf[3];
    for (int b = 0; b < 3; b++)
        ebuf[b] = base + (size_t)b * NN * DD;
    __half* e0hbuf[2] = { h0base, h0base + (size_t)NN * DD };
    __half* e1hbuf[2] = { h1base, h1base + (size_t)NN * DD };

    // L0: zero + mirrors + flags
    k_pre<<<(NN * DD / 4 + 255) / 256, 256>>>((const float4*)emb0);

    // L1: layer-0 MLPs + degree count
    k_mlp<<<792, 256>>>(emb0, emb0, eW1, eb1, mW1, mb1, mW2, mb2, ngum, hI);

    // L2: CSR scan+fill overlapped with layer-0 edge weights
    k_build_edgew<<<L2_GRID, 256>>>(hI, tI, G, egum, eW2, eb2);

    // L3: layer-0 gather  <-- profiled launch (index 3)
    k_gather<<<3125, 256>>>(emb0, emb0, emb0, e0hbuf[0], e1hbuf[0],
                            ebuf[0], ebuf[1], ebuf[2],
                            e0hbuf[1], e1hbuf[1],
                            emb0, out, wbase, 0, 0);

    // L4: layer-1 MLPs
    k_mlp<<<592, 256>>>(ebuf[1], ebuf[2],
                        eW1 + 128 * 64, eb1 + 64,
                        mW1 + 64 * 64, mb1 + 64, mW2 + 64 * 64, mb2 + 64,
                        ngum + (size_t)NN * 64, hI);

    // L5: layer-1 edge weights (CSR order)
    k_edgew_csr<<<1184, 256>>>(eW2 + 64);

    // L6: layer-1 gather + final output
    k_gather<<<3125, 256>>>(ebuf[0], ebuf[1], ebuf[2], e0hbuf[1], e1hbuf[1],
                            ebuf[0], ebuf[1], ebuf[2],
                            e0hbuf[0], e1hbuf[0],
                            emb0, out, wcsrbase, 1, 1);
}